// round 7
// baseline (speedup 1.0000x reference)
#include <cuda_runtime.h>
#include <cuda_bf16.h>
#include <cuda_fp16.h>
#include <math.h>
#include <cstdint>

#define Bq   128
#define Tq   256
#define Eq   512
#define Hq   1024
#define TOPq 128
#define Fq   512
#define Oq   10
#define G4   4096
#define NH   8
#define BH   (Bq * Hq)

typedef unsigned long long u64;
typedef unsigned int u32;

// ---------------- device scratch ----------------
__device__ float g_xg[(size_t)Bq * Tq * G4];
__device__ float g_tb[Bq * G4];
__device__ float g_hbuf[Bq * Hq];
__device__ __half g_h16hi[2 * BH];                 // f16(h)
__device__ __half g_h16lo[2 * BH];                 // f16((h - f16(h)) * 32)
__device__ __half g_w16[(size_t)G4 * Hq];          // f16(w_hh)
__device__ __half g_w16s[(size_t)G4 * Hq];         // f16(w_hh / 32)
__device__ __nv_bfloat16 g_xeb[(size_t)Bq * Tq * Eq];
__device__ __nv_bfloat16 g_wihb[(size_t)G4 * Eq];
__device__ float g_h1[Bq * Fq];
__device__ float g_s[Fq];
__device__ float g_t[Fq];
__device__ unsigned int g_bar;

// ---------------- helpers ----------------
__device__ __forceinline__ float sigmoidf(float x) { return 1.0f / (1.0f + expf(-x)); }

__device__ __forceinline__ u32 smem_u32(const void* p) {
    u32 a; asm("{ .reg .u64 t; cvta.to.shared.u64 t, %1; cvt.u32.u64 %0, t; }" : "=r"(a) : "l"(p));
    return a;
}
__device__ __forceinline__ void ldm4(u32 &r0, u32 &r1, u32 &r2, u32 &r3, u32 addr) {
    asm volatile("ldmatrix.sync.aligned.m8n8.x4.shared.b16 {%0,%1,%2,%3}, [%4];"
        : "=r"(r0), "=r"(r1), "=r"(r2), "=r"(r3) : "r"(addr));
}
__device__ __forceinline__ void mma16816(float* d, const u32* a, u32 b0, u32 b1) {
    asm volatile("mma.sync.aligned.m16n8k16.row.col.f32.bf16.bf16.f32 "
        "{%0,%1,%2,%3}, {%4,%5,%6,%7}, {%8,%9}, {%0,%1,%2,%3};"
        : "+f"(d[0]), "+f"(d[1]), "+f"(d[2]), "+f"(d[3])
        : "r"(a[0]), "r"(a[1]), "r"(a[2]), "r"(a[3]), "r"(b0), "r"(b1));
}
__device__ __forceinline__ void mma16816h(float* d, const u32* a, u32 b0, u32 b1) {
    asm volatile("mma.sync.aligned.m16n8k16.row.col.f32.f16.f16.f32 "
        "{%0,%1,%2,%3}, {%4,%5,%6,%7}, {%8,%9}, {%0,%1,%2,%3};"
        : "+f"(d[0]), "+f"(d[1]), "+f"(d[2]), "+f"(d[3])
        : "r"(a[0]), "r"(a[1]), "r"(a[2]), "r"(a[3]), "r"(b0), "r"(b1));
}
__device__ __forceinline__ void cpa16(u32 dst, const void* src) {
    asm volatile("cp.async.cg.shared.global [%0], [%1], 16;" :: "r"(dst), "l"(src));
}
#define CP_COMMIT() asm volatile("cp.async.commit_group;" ::: "memory")
#define CP_WAIT0()  asm volatile("cp.async.wait_group 0;" ::: "memory")

// ---------------- init ----------------
__global__ void k_init() {
    int i = blockIdx.x * blockDim.x + threadIdx.x;
    if (i == 0) g_bar = 0u;
    if (i < BH) {
        g_h16hi[i] = __float2half(0.f);
        g_h16lo[i] = __float2half(0.f);
    }
}

// ---------------- w_hh prep: f16(w) and f16(w/32) ----------------
__global__ __launch_bounds__(256) void k_wprep(const float* __restrict__ w) {
    size_t i = ((size_t)blockIdx.x * 256 + threadIdx.x) * 4;
    float4 v = *(const float4*)(w + i);
    float vv[4] = {v.x, v.y, v.z, v.w};
    __half a[4], b[4];
    #pragma unroll
    for (int j = 0; j < 4; j++) {
        a[j] = __float2half_rn(vv[j]);
        b[j] = __float2half_rn(vv[j] * (1.0f / 32.0f));
    }
    *(uint2*)(g_w16 + i)  = *(uint2*)a;
    *(uint2*)(g_w16s + i) = *(uint2*)b;
}

// ---------------- w_ih -> bf16 ----------------
__global__ __launch_bounds__(256) void k_wihb(const float* __restrict__ w) {
    size_t i = ((size_t)blockIdx.x * 256 + threadIdx.x) * 4;
    float4 v = *(const float4*)(w + i);
    __nv_bfloat16 b[4] = {__float2bfloat16(v.x), __float2bfloat16(v.y),
                          __float2bfloat16(v.z), __float2bfloat16(v.w)};
    *(uint2*)(g_wihb + i) = *(uint2*)b;
}

// ---------------- emb gather -> bf16 ----------------
__global__ __launch_bounds__(256) void k_xeb(const int* __restrict__ x,
                                             const float* __restrict__ emb) {
    size_t idx = (size_t)blockIdx.x * 256 + threadIdx.x;
    int m = (int)(idx >> 7);
    int e4 = ((int)idx & 127) * 4;
    int row = x[m];
    float4 v = *(const float4*)(emb + (size_t)row * Eq + e4);
    __nv_bfloat16 b[4] = {__float2bfloat16(v.x), __float2bfloat16(v.y),
                          __float2bfloat16(v.z), __float2bfloat16(v.w)};
    *(uint2*)(g_xeb + (size_t)m * Eq + e4) = *(uint2*)b;
}

// ---------------- topic bias ----------------
__global__ __launch_bounds__(256) void k_topic(const float* __restrict__ x_top,
                                               const float* __restrict__ w_th,
                                               const float* __restrict__ bias) {
    __shared__ float xt[TOPq];
    int b = blockIdx.x, tid = threadIdx.x;
    if (tid < TOPq) xt[tid] = x_top[b * TOPq + tid];
    __syncthreads();
    for (int g = tid; g < G4; g += 256) {
        const float4* wr = (const float4*)(w_th + (size_t)g * TOPq);
        float s = bias[g];
        #pragma unroll
        for (int k = 0; k < TOPq / 4; k++) {
            float4 w4 = wr[k];
            s += xt[4*k]*w4.x + xt[4*k+1]*w4.y + xt[4*k+2]*w4.z + xt[4*k+3]*w4.w;
        }
        g_tb[b * G4 + g] = s;
    }
}

// ---------------- xg GEMM (bf16 tensor, cp.async; unchanged from R5) -------
#define XA_STRIDE 144
#define XA_HALF   18432
#define XB_BASE   36864
#define XB_HALF   9216
#define XG_SMEM   55296

__global__ __launch_bounds__(256) void k_xg_t() {
    extern __shared__ char dsm[];
    int tid = threadIdx.x, wid = tid >> 5, lane = tid & 31;
    int n0 = blockIdx.x * 64;
    int m0 = blockIdx.y * 128;

    int arow[4], ac[4];
    #pragma unroll
    for (int i = 0; i < 4; i++) { int u = tid + i * 256; arow[i] = u >> 3; ac[i] = u & 7; }
    int brow[2], bc[2];
    #pragma unroll
    for (int i = 0; i < 2; i++) { int u = tid + i * 256; brow[i] = u >> 3; bc[i] = u & 7; }

    u32 sb = smem_u32(dsm);
    int amrow = wid * 16 + (lane & 7) + ((lane >> 3) & 1) * 8;
    u32 aAddr = sb + amrow * XA_STRIDE + (lane >> 4) * 16;
    u32 bAddr = sb + XB_BASE + lane * XA_STRIDE;

    float acc[8][4];
    #pragma unroll
    for (int i = 0; i < 8; i++) { acc[i][0]=0.f; acc[i][1]=0.f; acc[i][2]=0.f; acc[i][3]=0.f; }

    const __nv_bfloat16* Ag = g_xeb + (size_t)m0 * Eq;
    const __nv_bfloat16* Bg = g_wihb + (size_t)n0 * Eq;

    {
        u32 aS = sb, bS = sb + XB_BASE;
        #pragma unroll
        for (int i = 0; i < 4; i++)
            cpa16(aS + arow[i] * XA_STRIDE + ac[i] * 16, Ag + (size_t)arow[i] * Eq + ac[i] * 8);
        #pragma unroll
        for (int i = 0; i < 2; i++)
            cpa16(bS + brow[i] * XA_STRIDE + bc[i] * 16, Bg + (size_t)brow[i] * Eq + bc[i] * 8);
        CP_COMMIT();
    }

    for (int c = 0; c < 8; c++) {
        int buf = c & 1;
        CP_WAIT0();
        __syncthreads();
        if (c < 7) {
            int k0 = (c + 1) * 64;
            u32 aS = sb + (buf ^ 1) * XA_HALF;
            u32 bS = sb + XB_BASE + (buf ^ 1) * XB_HALF;
            #pragma unroll
            for (int i = 0; i < 4; i++)
                cpa16(aS + arow[i] * XA_STRIDE + ac[i] * 16, Ag + (size_t)arow[i] * Eq + k0 + ac[i] * 8);
            #pragma unroll
            for (int i = 0; i < 2; i++)
                cpa16(bS + brow[i] * XA_STRIDE + bc[i] * 16, Bg + (size_t)brow[i] * Eq + k0 + bc[i] * 8);
            CP_COMMIT();
        }

        u32 oA = buf * XA_HALF, oB = buf * XB_HALF;
        #pragma unroll
        for (int s = 0; s < 4; s++) {
            u32 a[4], b0[4], b1[4], b2[4], b3[4];
            ldm4(a[0], a[1], a[2], a[3], aAddr + oA + s * 32);
            ldm4(b0[0], b0[1], b0[2], b0[3], bAddr + oB + s * 32);
            ldm4(b1[0], b1[1], b1[2], b1[3], bAddr + oB + s * 32 + 16);
            ldm4(b2[0], b2[1], b2[2], b2[3], bAddr + 4608 + oB + s * 32);
            ldm4(b3[0], b3[1], b3[2], b3[3], bAddr + 4608 + oB + s * 32 + 16);
            #pragma unroll
            for (int nt = 0; nt < 4; nt++) mma16816(acc[nt], a, b0[nt], b1[nt]);
            #pragma unroll
            for (int nt = 0; nt < 4; nt++) mma16816(acc[4 + nt], a, b2[nt], b3[nt]);
        }
    }

    int g = lane >> 2, tq = lane & 3;
    int bb = m0 >> 8;
    const float* tbr = g_tb + (size_t)bb * G4 + n0;
    #pragma unroll
    for (int rr = 0; rr < 2; rr++) {
        int m = m0 + wid * 16 + g + rr * 8;
        float* orow = g_xg + (size_t)m * G4 + n0;
        #pragma unroll
        for (int nt = 0; nt < 8; nt++) {
            int nn = nt * 8 + tq * 2;
            float2 tb2 = *(const float2*)(tbr + nn);
            float2 o;
            o.x = acc[nt][rr * 2 + 0] + tb2.x;
            o.y = acc[nt][rr * 2 + 1] + tb2.y;
            *(float2*)(orow + nn) = o;
        }
    }
}

// ---------------- persistent LSTM recurrence: fp16 2-unit ----------------
// gate = h_hi(f16)·w16 + (h_lo*32)(f16)·(w/32)(f16), one f32 accumulator.
// 32 chunks of K=64: c<16 -> (h_hi, w16 bank), c>=16 -> (h_lo_s, w16s bank).
// Smem: A double-buf 2 x 18432 = 36864; B persistent 32 x 4608 = 147456.
#define RA      0
#define RAB     18432
#define RB      36864
#define RNN_SMEM 184320

__global__ __launch_bounds__(256) void k_rnn() {
    extern __shared__ char dsm[];
    int tid = threadIdx.x, wid = tid >> 5, lane = tid & 31;
    int n = blockIdx.x;
    u32 sb = smem_u32(dsm);

    int arow[4], ac[4];
    #pragma unroll
    for (int i = 0; i < 4; i++) { int u = tid + i * 256; arow[i] = u >> 3; ac[i] = u & 7; }

    // ---- persistent B: bank 0 = w16 (chunks 0-15), bank 1 = w16s (16-31) ----
    {
        int brow = tid >> 3, bc = tid & 7;
        size_t grow = (size_t)((brow >> 3) * Hq + n * NH + (brow & 7)) * Hq;
        u32 d = sb + RB + brow * 144 + bc * 16;
        #pragma unroll
        for (int cc = 0; cc < 16; cc++) {
            cpa16(d + cc * 4608,        g_w16  + grow + cc * 64 + bc * 8);
            cpa16(d + (16 + cc) * 4608, g_w16s + grow + cc * 64 + bc * 8);
        }
        CP_COMMIT();
    }

    int amrow = wid * 16 + (lane & 7) + ((lane >> 3) & 1) * 8;
    u32 aAddr = sb + RA + amrow * 144 + (lane >> 4) * 16;
    u32 bAddr = sb + RB + lane * 144;

    int g = lane >> 2, tq = lane & 3;
    int u0 = tq * 2;
    float creg[4] = {0.f, 0.f, 0.f, 0.f};

    CP_WAIT0();
    __syncthreads();

    for (int t = 0; t < Tq; t++) {
        int ph = t & 1;
        const __half* hh = g_h16hi + (size_t)ph * BH;
        const __half* hl = g_h16lo + (size_t)ph * BH;

        float acc[4][4];
        #pragma unroll
        for (int i = 0; i < 4; i++) { acc[i][0]=0.f; acc[i][1]=0.f; acc[i][2]=0.f; acc[i][3]=0.f; }

        // issue chunk 0 (h_hi, k=0..63) into buf 0
        {
            u32 d = sb + RA;
            #pragma unroll
            for (int i = 0; i < 4; i++)
                cpa16(d + arow[i] * 144 + ac[i] * 16, hh + (size_t)arow[i] * Hq + ac[i] * 8);
            CP_COMMIT();
        }

        for (int c = 0; c < 32; c++) {
            int buf = c & 1;
            CP_WAIT0();
            __syncthreads();
            if (c < 31) {
                int cn = c + 1;
                const __half* src = (cn < 16) ? hh : hl;
                int k0 = (cn & 15) * 64;
                u32 d = sb + RA + (buf ^ 1) * RAB;
                #pragma unroll
                for (int i = 0; i < 4; i++)
                    cpa16(d + arow[i] * 144 + ac[i] * 16, src + (size_t)arow[i] * Hq + k0 + ac[i] * 8);
                CP_COMMIT();
            }

            u32 oA = buf * RAB;
            u32 oB = c * 4608;
            #pragma unroll
            for (int s = 0; s < 4; s++) {
                u32 a[4], b0[4], b1[4];
                ldm4(a[0], a[1], a[2], a[3], aAddr + oA + s * 32);
                ldm4(b0[0], b0[1], b0[2], b0[3], bAddr + oB + s * 32);
                ldm4(b1[0], b1[1], b1[2], b1[3], bAddr + oB + s * 32 + 16);
                #pragma unroll
                for (int nt = 0; nt < 4; nt++) mma16816h(acc[nt], a, b0[nt], b1[nt]);
            }
        }

        // ---- epilogue (registers only; c persistent) ----
        int phn = (t + 1) & 1;
        #pragma unroll
        for (int rr = 0; rr < 2; rr++) {
            int b = wid * 16 + g + rr * 8;
            const float* xr = g_xg + ((size_t)b * Tq + t) * G4 + n * NH + u0;
            float2 x0 = *(const float2*)(xr);
            float2 x1 = *(const float2*)(xr + Hq);
            float2 x2 = *(const float2*)(xr + 2 * Hq);
            float2 x3 = *(const float2*)(xr + 3 * Hq);

            float i0 = sigmoidf(acc[0][rr*2+0] + x0.x);
            float f0 = sigmoidf(acc[1][rr*2+0] + x1.x);
            float gg0 = tanhf(acc[2][rr*2+0] + x2.x);
            float o0 = sigmoidf(acc[3][rr*2+0] + x3.x);
            float i1 = sigmoidf(acc[0][rr*2+1] + x0.y);
            float f1 = sigmoidf(acc[1][rr*2+1] + x1.y);
            float gg1 = tanhf(acc[2][rr*2+1] + x2.y);
            float o1 = sigmoidf(acc[3][rr*2+1] + x3.y);

            float c0 = f0 * creg[rr*2+0] + i0 * gg0;
            float c1 = f1 * creg[rr*2+1] + i1 * gg1;
            creg[rr*2+0] = c0;
            creg[rr*2+1] = c1;
            float hx = o0 * tanhf(c0);
            float hy = o1 * tanhf(c1);

            size_t hob = (size_t)phn * BH + (size_t)b * Hq + n * NH + u0;
            __half hi0 = __float2half_rn(hx);
            __half hi1 = __float2half_rn(hy);
            __half lo0 = __float2half_rn((hx - __half2float(hi0)) * 32.0f);
            __half lo1 = __float2half_rn((hy - __half2float(hi1)) * 32.0f);
            __half2 hp = __halves2half2(hi0, hi1);
            __half2 lp = __halves2half2(lo0, lo1);
            __stcg((unsigned int*)(g_h16hi + hob), *(unsigned int*)&hp);
            __stcg((unsigned int*)(g_h16lo + hob), *(unsigned int*)&lp);

            if (t == Tq - 1) {
                float2 hv; hv.x = hx; hv.y = hy;
                *(float2*)(g_hbuf + (size_t)b * Hq + n * NH + u0) = hv;
            }
        }

        // ---- global barrier between steps ----
        if (t < Tq - 1) {
            __threadfence();
            __syncthreads();
            if (tid == 0) {
                atomicAdd(&g_bar, 1u);
                unsigned int tgt = 128u * (t + 1);
                volatile unsigned int* p = &g_bar;
                while (*p < tgt) { }
                __threadfence();
            }
            __syncthreads();
        }
    }
}

// ---------------- fc1 ----------------
__global__ __launch_bounds__(256) void k_fc1(const float* __restrict__ fc1_w,
                                             const float* __restrict__ fc1_b) {
    int b = blockIdx.y;
    int f = blockIdx.x * 8 + (threadIdx.x >> 5);
    int lane = threadIdx.x & 31;
    const float* hr = g_hbuf + (size_t)b * Hq;
    const float* wr = fc1_w + (size_t)f * Hq;
    float s = 0.f;
    for (int k = lane; k < Hq; k += 32) s += hr[k] * wr[k];
    #pragma unroll
    for (int off = 16; off; off >>= 1) s += __shfl_xor_sync(0xffffffffu, s, off);
    if (lane == 0) g_h1[b * Fq + f] = s + fc1_b[f];
}

// ---------------- BN stats ----------------
__global__ void k_bn(const float* __restrict__ gamma, const float* __restrict__ beta) {
    int f = threadIdx.x;
    float s = 0.f, ss = 0.f;
    for (int b = 0; b < Bq; b++) { float v = g_h1[b * Fq + f]; s += v; ss += v * v; }
    float mu = s * (1.f / Bq);
    float var = ss * (1.f / Bq) - mu * mu;
    float rstd = rsqrtf(var + 1e-5f);
    float sc = rstd * gamma[f];
    g_s[f] = sc;
    g_t[f] = beta[f] - mu * sc;
}

// ---------------- fc2 ----------------
__global__ __launch_bounds__(320) void k_out(const float* __restrict__ fc2_w,
                                             const float* __restrict__ fc2_b,
                                             float* __restrict__ out) {
    int b = blockIdx.x;
    int o = threadIdx.x >> 5;
    int lane = threadIdx.x & 31;
    const float* h1r = g_h1 + (size_t)b * Fq;
    const float* wr = fc2_w + (size_t)o * Fq;
    float s = 0.f;
    for (int f = lane; f < Fq; f += 32) s += (h1r[f] * g_s[f] + g_t[f]) * wr[f];
    #pragma unroll
    for (int off = 16; off; off >>= 1) s += __shfl_xor_sync(0xffffffffu, s, off);
    if (lane == 0) out[b * Oq + o] = s + fc2_b[o];
}

// ---------------- launch ----------------
extern "C" void kernel_launch(void* const* d_in, const int* in_sizes, int n_in,
                              void* d_out, int out_size) {
    const int*   x     = (const int*)  d_in[0];
    const float* x_top = (const float*)d_in[1];
    const float* emb   = (const float*)d_in[2];
    const float* w_ih  = (const float*)d_in[3];
    const float* w_hh  = (const float*)d_in[4];
    const float* w_th  = (const float*)d_in[5];
    const float* bias  = (const float*)d_in[6];
    const float* fc1_w = (const float*)d_in[7];
    const float* fc1_b = (const float*)d_in[8];
    const float* gamma = (const float*)d_in[9];
    const float* beta  = (const float*)d_in[10];
    const float* fc2_w = (const float*)d_in[11];
    const float* fc2_b = (const float*)d_in[12];
    float* out = (float*)d_out;

    cudaFuncSetAttribute(k_xg_t, cudaFuncAttributeMaxDynamicSharedMemorySize, XG_SMEM);
    cudaFuncSetAttribute(k_rnn,  cudaFuncAttributeMaxDynamicSharedMemorySize, RNN_SMEM);

    k_init<<<(BH + 255) / 256, 256>>>();
    k_wprep<<<(G4 * Hq / 4) / 256, 256>>>(w_hh);
    k_wihb<<<(G4 * Eq / 4) / 256, 256>>>(w_ih);
    k_xeb<<<(Bq * Tq * Eq / 4) / 256, 256>>>(x, emb);
    k_topic<<<Bq, 256>>>(x_top, w_th, bias);
    dim3 gxg(G4 / 64, (Bq * Tq) / 128);
    k_xg_t<<<gxg, 256, XG_SMEM>>>();
    k_rnn<<<128, 256, RNN_SMEM>>>();
    k_fc1<<<dim3(Fq / 8, Bq), 256>>>(fc1_w, fc1_b);
    k_bn<<<1, Fq>>>(gamma, beta);
    k_out<<<Bq, 320>>>(fc2_w, fc2_b, out);
}

// round 8
// speedup vs baseline: 1.3070x; 1.3070x over previous
#include <cuda_runtime.h>
#include <cuda_bf16.h>
#include <cuda_fp16.h>
#include <math.h>
#include <cstdint>

#define Bq   128
#define Tq   256
#define Eq   512
#define Hq   1024
#define TOPq 128
#define Fq   512
#define Oq   10
#define G4   4096
#define NH   8
#define BH   (Bq * Hq)

typedef unsigned long long u64;
typedef unsigned int u32;

// ---------------- device scratch ----------------
__device__ float g_xg[(size_t)Bq * Tq * G4];
__device__ float g_tb[Bq * G4];
__device__ float g_hbuf[Bq * Hq];
__device__ __half g_h16hi[2 * BH];                 // f16(h)
__device__ __half g_h16lo[2 * BH];                 // f16((h - f16(h)) * 32)
__device__ __half g_w16[(size_t)G4 * Hq];          // f16(w_hh)
__device__ __half g_w16s[(size_t)G4 * Hq];         // f16(w_hh / 32)
__device__ __nv_bfloat16 g_xeb[(size_t)Bq * Tq * Eq];
__device__ __nv_bfloat16 g_wihb[(size_t)G4 * Eq];
__device__ float g_h1[Bq * Fq];
__device__ float g_s[Fq];
__device__ float g_t[Fq];
__device__ unsigned int g_bar;

// ---------------- helpers ----------------
__device__ __forceinline__ float sigmoidf(float x) { return 1.0f / (1.0f + expf(-x)); }

__device__ __forceinline__ u32 smem_u32(const void* p) {
    u32 a; asm("{ .reg .u64 t; cvta.to.shared.u64 t, %1; cvt.u32.u64 %0, t; }" : "=r"(a) : "l"(p));
    return a;
}
__device__ __forceinline__ void ldm4(u32 &r0, u32 &r1, u32 &r2, u32 &r3, u32 addr) {
    asm volatile("ldmatrix.sync.aligned.m8n8.x4.shared.b16 {%0,%1,%2,%3}, [%4];"
        : "=r"(r0), "=r"(r1), "=r"(r2), "=r"(r3) : "r"(addr));
}
__device__ __forceinline__ void mma16816(float* d, const u32* a, u32 b0, u32 b1) {
    asm volatile("mma.sync.aligned.m16n8k16.row.col.f32.bf16.bf16.f32 "
        "{%0,%1,%2,%3}, {%4,%5,%6,%7}, {%8,%9}, {%0,%1,%2,%3};"
        : "+f"(d[0]), "+f"(d[1]), "+f"(d[2]), "+f"(d[3])
        : "r"(a[0]), "r"(a[1]), "r"(a[2]), "r"(a[3]), "r"(b0), "r"(b1));
}
__device__ __forceinline__ void mma16816h(float* d, const u32* a, u32 b0, u32 b1) {
    asm volatile("mma.sync.aligned.m16n8k16.row.col.f32.f16.f16.f32 "
        "{%0,%1,%2,%3}, {%4,%5,%6,%7}, {%8,%9}, {%0,%1,%2,%3};"
        : "+f"(d[0]), "+f"(d[1]), "+f"(d[2]), "+f"(d[3])
        : "r"(a[0]), "r"(a[1]), "r"(a[2]), "r"(a[3]), "r"(b0), "r"(b1));
}
__device__ __forceinline__ void cpa16(u32 dst, const void* src) {
    asm volatile("cp.async.cg.shared.global [%0], [%1], 16;" :: "r"(dst), "l"(src));
}
#define CP_COMMIT() asm volatile("cp.async.commit_group;" ::: "memory")
#define CP_WAIT0()  asm volatile("cp.async.wait_group 0;" ::: "memory")

// ---------------- init ----------------
__global__ void k_init() {
    int i = blockIdx.x * blockDim.x + threadIdx.x;
    if (i == 0) g_bar = 0u;
    if (i < BH) {
        g_h16hi[i] = __float2half(0.f);
        g_h16lo[i] = __float2half(0.f);
    }
}

// ---------------- w_hh prep: f16(w) and f16(w/32) ----------------
__global__ __launch_bounds__(256) void k_wprep(const float* __restrict__ w) {
    size_t i = ((size_t)blockIdx.x * 256 + threadIdx.x) * 4;
    float4 v = *(const float4*)(w + i);
    float vv[4] = {v.x, v.y, v.z, v.w};
    __half a[4], b[4];
    #pragma unroll
    for (int j = 0; j < 4; j++) {
        a[j] = __float2half_rn(vv[j]);
        b[j] = __float2half_rn(vv[j] * (1.0f / 32.0f));
    }
    *(uint2*)(g_w16 + i)  = *(uint2*)a;
    *(uint2*)(g_w16s + i) = *(uint2*)b;
}

// ---------------- w_ih -> bf16 ----------------
__global__ __launch_bounds__(256) void k_wihb(const float* __restrict__ w) {
    size_t i = ((size_t)blockIdx.x * 256 + threadIdx.x) * 4;
    float4 v = *(const float4*)(w + i);
    __nv_bfloat16 b[4] = {__float2bfloat16(v.x), __float2bfloat16(v.y),
                          __float2bfloat16(v.z), __float2bfloat16(v.w)};
    *(uint2*)(g_wihb + i) = *(uint2*)b;
}

// ---------------- emb gather -> bf16 ----------------
__global__ __launch_bounds__(256) void k_xeb(const int* __restrict__ x,
                                             const float* __restrict__ emb) {
    size_t idx = (size_t)blockIdx.x * 256 + threadIdx.x;
    int m = (int)(idx >> 7);
    int e4 = ((int)idx & 127) * 4;
    int row = x[m];
    float4 v = *(const float4*)(emb + (size_t)row * Eq + e4);
    __nv_bfloat16 b[4] = {__float2bfloat16(v.x), __float2bfloat16(v.y),
                          __float2bfloat16(v.z), __float2bfloat16(v.w)};
    *(uint2*)(g_xeb + (size_t)m * Eq + e4) = *(uint2*)b;
}

// ---------------- topic bias ----------------
__global__ __launch_bounds__(256) void k_topic(const float* __restrict__ x_top,
                                               const float* __restrict__ w_th,
                                               const float* __restrict__ bias) {
    __shared__ float xt[TOPq];
    int b = blockIdx.x, tid = threadIdx.x;
    if (tid < TOPq) xt[tid] = x_top[b * TOPq + tid];
    __syncthreads();
    for (int g = tid; g < G4; g += 256) {
        const float4* wr = (const float4*)(w_th + (size_t)g * TOPq);
        float s = bias[g];
        #pragma unroll
        for (int k = 0; k < TOPq / 4; k++) {
            float4 w4 = wr[k];
            s += xt[4*k]*w4.x + xt[4*k+1]*w4.y + xt[4*k+2]*w4.z + xt[4*k+3]*w4.w;
        }
        g_tb[b * G4 + g] = s;
    }
}

// ---------------- xg GEMM (bf16 tensor, cp.async; unchanged) ----------------
#define XA_STRIDE 144
#define XA_HALF   18432
#define XB_BASE   36864
#define XB_HALF   9216
#define XG_SMEM   55296

__global__ __launch_bounds__(256) void k_xg_t() {
    extern __shared__ char dsm[];
    int tid = threadIdx.x, wid = tid >> 5, lane = tid & 31;
    int n0 = blockIdx.x * 64;
    int m0 = blockIdx.y * 128;

    int arow[4], ac[4];
    #pragma unroll
    for (int i = 0; i < 4; i++) { int u = tid + i * 256; arow[i] = u >> 3; ac[i] = u & 7; }
    int brow[2], bc[2];
    #pragma unroll
    for (int i = 0; i < 2; i++) { int u = tid + i * 256; brow[i] = u >> 3; bc[i] = u & 7; }

    u32 sb = smem_u32(dsm);
    int amrow = wid * 16 + (lane & 7) + ((lane >> 3) & 1) * 8;
    u32 aAddr = sb + amrow * XA_STRIDE + (lane >> 4) * 16;
    u32 bAddr = sb + XB_BASE + lane * XA_STRIDE;

    float acc[8][4];
    #pragma unroll
    for (int i = 0; i < 8; i++) { acc[i][0]=0.f; acc[i][1]=0.f; acc[i][2]=0.f; acc[i][3]=0.f; }

    const __nv_bfloat16* Ag = g_xeb + (size_t)m0 * Eq;
    const __nv_bfloat16* Bg = g_wihb + (size_t)n0 * Eq;

    {
        u32 aS = sb, bS = sb + XB_BASE;
        #pragma unroll
        for (int i = 0; i < 4; i++)
            cpa16(aS + arow[i] * XA_STRIDE + ac[i] * 16, Ag + (size_t)arow[i] * Eq + ac[i] * 8);
        #pragma unroll
        for (int i = 0; i < 2; i++)
            cpa16(bS + brow[i] * XA_STRIDE + bc[i] * 16, Bg + (size_t)brow[i] * Eq + bc[i] * 8);
        CP_COMMIT();
    }

    for (int c = 0; c < 8; c++) {
        int buf = c & 1;
        CP_WAIT0();
        __syncthreads();
        if (c < 7) {
            int k0 = (c + 1) * 64;
            u32 aS = sb + (buf ^ 1) * XA_HALF;
            u32 bS = sb + XB_BASE + (buf ^ 1) * XB_HALF;
            #pragma unroll
            for (int i = 0; i < 4; i++)
                cpa16(aS + arow[i] * XA_STRIDE + ac[i] * 16, Ag + (size_t)arow[i] * Eq + k0 + ac[i] * 8);
            #pragma unroll
            for (int i = 0; i < 2; i++)
                cpa16(bS + brow[i] * XA_STRIDE + bc[i] * 16, Bg + (size_t)brow[i] * Eq + k0 + bc[i] * 8);
            CP_COMMIT();
        }

        u32 oA = buf * XA_HALF, oB = buf * XB_HALF;
        #pragma unroll
        for (int s = 0; s < 4; s++) {
            u32 a[4], b0[4], b1[4], b2[4], b3[4];
            ldm4(a[0], a[1], a[2], a[3], aAddr + oA + s * 32);
            ldm4(b0[0], b0[1], b0[2], b0[3], bAddr + oB + s * 32);
            ldm4(b1[0], b1[1], b1[2], b1[3], bAddr + oB + s * 32 + 16);
            ldm4(b2[0], b2[1], b2[2], b2[3], bAddr + 4608 + oB + s * 32);
            ldm4(b3[0], b3[1], b3[2], b3[3], bAddr + 4608 + oB + s * 32 + 16);
            #pragma unroll
            for (int nt = 0; nt < 4; nt++) mma16816(acc[nt], a, b0[nt], b1[nt]);
            #pragma unroll
            for (int nt = 0; nt < 4; nt++) mma16816(acc[4 + nt], a, b2[nt], b3[nt]);
        }
    }

    int g = lane >> 2, tq = lane & 3;
    int bb = m0 >> 8;
    const float* tbr = g_tb + (size_t)bb * G4 + n0;
    #pragma unroll
    for (int rr = 0; rr < 2; rr++) {
        int m = m0 + wid * 16 + g + rr * 8;
        float* orow = g_xg + (size_t)m * G4 + n0;
        #pragma unroll
        for (int nt = 0; nt < 8; nt++) {
            int nn = nt * 8 + tq * 2;
            float2 tb2 = *(const float2*)(tbr + nn);
            float2 o;
            o.x = acc[nt][rr * 2 + 0] + tb2.x;
            o.y = acc[nt][rr * 2 + 1] + tb2.y;
            *(float2*)(orow + nn) = o;
        }
    }
}

// ---------------- persistent LSTM recurrence: fp16 2-pass, 16 chunks -------
// gate = h_hi(f16)·w16 + (h_lo*32)(f16)·(w/32)(f16); scales cancel in f32 acc.
// Smem: A double-buffer 2 x (hi 18432 + lo 18432) = 73728
//       B persistent: w16 16 x 4608 + w16s 16 x 4608 = 147456  -> 221184
#define A_STRIDE 144
#define A_BUF    36864
#define A_LO     18432
#define BP_BASE  73728
#define BP_S     73728     // offset of w16s bank relative to BP_BASE
#define RNN_SMEM 221184

__global__ __launch_bounds__(256) void k_rnn() {
    extern __shared__ char dsm[];
    int tid = threadIdx.x, wid = tid >> 5, lane = tid & 31;
    int n = blockIdx.x;
    u32 sb = smem_u32(dsm);

    int arow[4], ac[4];
    #pragma unroll
    for (int i = 0; i < 4; i++) { int u = tid + i * 256; arow[i] = u >> 3; ac[i] = u & 7; }

    // ---- persistent B: bank0 = w16, bank1 = w16s ----
    {
        int brow = tid >> 3, bc = tid & 7;
        size_t grow = (size_t)((brow >> 3) * Hq + n * NH + (brow & 7)) * Hq;
        u32 d = sb + BP_BASE + brow * A_STRIDE + bc * 16;
        #pragma unroll
        for (int c = 0; c < 16; c++) {
            cpa16(d + c * 4608,        g_w16  + grow + c * 64 + bc * 8);
            cpa16(d + BP_S + c * 4608, g_w16s + grow + c * 64 + bc * 8);
        }
        CP_COMMIT();
    }

    int amrow = wid * 16 + (lane & 7) + ((lane >> 3) & 1) * 8;
    u32 aAddr = sb + amrow * A_STRIDE + (lane >> 4) * 16;
    u32 bAddr = sb + BP_BASE + lane * A_STRIDE;

    int g = lane >> 2, tq = lane & 3;
    int u0 = tq * 2;
    float creg[4] = {0.f, 0.f, 0.f, 0.f};

    CP_WAIT0();
    __syncthreads();

    for (int t = 0; t < Tq; t++) {
        int ph = t & 1;
        const __half* hh = g_h16hi + (size_t)ph * BH;
        const __half* hl = g_h16lo + (size_t)ph * BH;

        float acc[4][4];
        #pragma unroll
        for (int i = 0; i < 4; i++) { acc[i][0]=0.f; acc[i][1]=0.f; acc[i][2]=0.f; acc[i][3]=0.f; }

        // issue chunk 0 into buf 0 (hi + lo together)
        {
            u32 aH = sb, aL = sb + A_LO;
            #pragma unroll
            for (int i = 0; i < 4; i++) {
                size_t off = (size_t)arow[i] * Hq + ac[i] * 8;
                u32 so = arow[i] * A_STRIDE + ac[i] * 16;
                cpa16(aH + so, hh + off);
                cpa16(aL + so, hl + off);
            }
            CP_COMMIT();
        }

        for (int c = 0; c < 16; c++) {
            int buf = c & 1;
            CP_WAIT0();
            __syncthreads();
            if (c < 15) {
                int k0 = (c + 1) * 64;
                u32 aH = sb + (buf ^ 1) * A_BUF, aL = aH + A_LO;
                #pragma unroll
                for (int i = 0; i < 4; i++) {
                    size_t off = (size_t)arow[i] * Hq + k0 + ac[i] * 8;
                    u32 so = arow[i] * A_STRIDE + ac[i] * 16;
                    cpa16(aH + so, hh + off);
                    cpa16(aL + so, hl + off);
                }
                CP_COMMIT();
            }

            u32 oAh = buf * A_BUF;
            u32 oAl = oAh + A_LO;
            u32 oB  = c * 4608;
            u32 oBs = BP_S + c * 4608;
            #pragma unroll
            for (int s = 0; s < 4; s++) {
                u32 ah[4], al[4], b0[4], b1[4], c0[4], c1[4];
                ldm4(ah[0], ah[1], ah[2], ah[3], aAddr + oAh + s * 32);
                ldm4(al[0], al[1], al[2], al[3], aAddr + oAl + s * 32);
                ldm4(b0[0], b0[1], b0[2], b0[3], bAddr + oB + s * 32);
                ldm4(b1[0], b1[1], b1[2], b1[3], bAddr + oB + s * 32 + 16);
                ldm4(c0[0], c0[1], c0[2], c0[3], bAddr + oBs + s * 32);
                ldm4(c1[0], c1[1], c1[2], c1[3], bAddr + oBs + s * 32 + 16);
                #pragma unroll
                for (int nt = 0; nt < 4; nt++) {
                    mma16816h(acc[nt], ah, b0[nt], b1[nt]);
                    mma16816h(acc[nt], al, c0[nt], c1[nt]);
                }
            }
        }

        // ---- epilogue (registers only; c persistent) ----
        int phn = (t + 1) & 1;
        #pragma unroll
        for (int rr = 0; rr < 2; rr++) {
            int b = wid * 16 + g + rr * 8;
            const float* xr = g_xg + ((size_t)b * Tq + t) * G4 + n * NH + u0;
            float2 x0 = *(const float2*)(xr);
            float2 x1 = *(const float2*)(xr + Hq);
            float2 x2 = *(const float2*)(xr + 2 * Hq);
            float2 x3 = *(const float2*)(xr + 3 * Hq);

            float i0 = sigmoidf(acc[0][rr*2+0] + x0.x);
            float f0 = sigmoidf(acc[1][rr*2+0] + x1.x);
            float gg0 = tanhf(acc[2][rr*2+0] + x2.x);
            float o0 = sigmoidf(acc[3][rr*2+0] + x3.x);
            float i1 = sigmoidf(acc[0][rr*2+1] + x0.y);
            float f1 = sigmoidf(acc[1][rr*2+1] + x1.y);
            float gg1 = tanhf(acc[2][rr*2+1] + x2.y);
            float o1 = sigmoidf(acc[3][rr*2+1] + x3.y);

            float c0 = f0 * creg[rr*2+0] + i0 * gg0;
            float c1 = f1 * creg[rr*2+1] + i1 * gg1;
            creg[rr*2+0] = c0;
            creg[rr*2+1] = c1;
            float hx = o0 * tanhf(c0);
            float hy = o1 * tanhf(c1);

            size_t hob = (size_t)phn * BH + (size_t)b * Hq + n * NH + u0;
            __half hi0 = __float2half_rn(hx);
            __half hi1 = __float2half_rn(hy);
            __half lo0 = __float2half_rn((hx - __half2float(hi0)) * 32.0f);
            __half lo1 = __float2half_rn((hy - __half2float(hi1)) * 32.0f);
            __half2 hp = __halves2half2(hi0, hi1);
            __half2 lp = __halves2half2(lo0, lo1);
            __stcg((unsigned int*)(g_h16hi + hob), *(unsigned int*)&hp);
            __stcg((unsigned int*)(g_h16lo + hob), *(unsigned int*)&lp);

            if (t == Tq - 1) {
                float2 hv; hv.x = hx; hv.y = hy;
                *(float2*)(g_hbuf + (size_t)b * Hq + n * NH + u0) = hv;
            }
        }

        // ---- global barrier between steps ----
        if (t < Tq - 1) {
            __threadfence();
            __syncthreads();
            if (tid == 0) {
                atomicAdd(&g_bar, 1u);
                unsigned int tgt = 128u * (t + 1);
                volatile unsigned int* p = &g_bar;
                while (*p < tgt) { }
                __threadfence();
            }
            __syncthreads();
        }
    }
}

// ---------------- fc1 ----------------
__global__ __launch_bounds__(256) void k_fc1(const float* __restrict__ fc1_w,
                                             const float* __restrict__ fc1_b) {
    int b = blockIdx.y;
    int f = blockIdx.x * 8 + (threadIdx.x >> 5);
    int lane = threadIdx.x & 31;
    const float* hr = g_hbuf + (size_t)b * Hq;
    const float* wr = fc1_w + (size_t)f * Hq;
    float s = 0.f;
    for (int k = lane; k < Hq; k += 32) s += hr[k] * wr[k];
    #pragma unroll
    for (int off = 16; off; off >>= 1) s += __shfl_xor_sync(0xffffffffu, s, off);
    if (lane == 0) g_h1[b * Fq + f] = s + fc1_b[f];
}

// ---------------- BN stats ----------------
__global__ void k_bn(const float* __restrict__ gamma, const float* __restrict__ beta) {
    int f = threadIdx.x;
    float s = 0.f, ss = 0.f;
    for (int b = 0; b < Bq; b++) { float v = g_h1[b * Fq + f]; s += v; ss += v * v; }
    float mu = s * (1.f / Bq);
    float var = ss * (1.f / Bq) - mu * mu;
    float rstd = rsqrtf(var + 1e-5f);
    float sc = rstd * gamma[f];
    g_s[f] = sc;
    g_t[f] = beta[f] - mu * sc;
}

// ---------------- fc2 ----------------
__global__ __launch_bounds__(320) void k_out(const float* __restrict__ fc2_w,
                                             const float* __restrict__ fc2_b,
                                             float* __restrict__ out) {
    int b = blockIdx.x;
    int o = threadIdx.x >> 5;
    int lane = threadIdx.x & 31;
    const float* h1r = g_h1 + (size_t)b * Fq;
    const float* wr = fc2_w + (size_t)o * Fq;
    float s = 0.f;
    for (int f = lane; f < Fq; f += 32) s += (h1r[f] * g_s[f] + g_t[f]) * wr[f];
    #pragma unroll
    for (int off = 16; off; off >>= 1) s += __shfl_xor_sync(0xffffffffu, s, off);
    if (lane == 0) out[b * Oq + o] = s + fc2_b[o];
}

// ---------------- launch ----------------
extern "C" void kernel_launch(void* const* d_in, const int* in_sizes, int n_in,
                              void* d_out, int out_size) {
    const int*   x     = (const int*)  d_in[0];
    const float* x_top = (const float*)d_in[1];
    const float* emb   = (const float*)d_in[2];
    const float* w_ih  = (const float*)d_in[3];
    const float* w_hh  = (const float*)d_in[4];
    const float* w_th  = (const float*)d_in[5];
    const float* bias  = (const float*)d_in[6];
    const float* fc1_w = (const float*)d_in[7];
    const float* fc1_b = (const float*)d_in[8];
    const float* gamma = (const float*)d_in[9];
    const float* beta  = (const float*)d_in[10];
    const float* fc2_w = (const float*)d_in[11];
    const float* fc2_b = (const float*)d_in[12];
    float* out = (float*)d_out;

    cudaFuncSetAttribute(k_xg_t, cudaFuncAttributeMaxDynamicSharedMemorySize, XG_SMEM);
    cudaFuncSetAttribute(k_rnn,  cudaFuncAttributeMaxDynamicSharedMemorySize, RNN_SMEM);

    k_init<<<(BH + 255) / 256, 256>>>();
    k_wprep<<<(G4 * Hq / 4) / 256, 256>>>(w_hh);
    k_wihb<<<(G4 * Eq / 4) / 256, 256>>>(w_ih);
    k_xeb<<<(Bq * Tq * Eq / 4) / 256, 256>>>(x, emb);
    k_topic<<<Bq, 256>>>(x_top, w_th, bias);
    dim3 gxg(G4 / 64, (Bq * Tq) / 128);
    k_xg_t<<<gxg, 256, XG_SMEM>>>();
    k_rnn<<<128, 256, RNN_SMEM>>>();
    k_fc1<<<dim3(Fq / 8, Bq), 256>>>(fc1_w, fc1_b);
    k_bn<<<1, Fq>>>(gamma, beta);
    k_out<<<Bq, 320>>>(fc2_w, fc2_b, out);
}

// round 9
// speedup vs baseline: 1.4546x; 1.1129x over previous
#include <cuda_runtime.h>
#include <cuda_bf16.h>
#include <cuda_fp16.h>
#include <math.h>
#include <cstdint>

#define Bq   128
#define Tq   256
#define Eq   512
#define Hq   1024
#define TOPq 128
#define Fq   512
#define Oq   10
#define G4   4096
#define NH   8
#define BH   (Bq * Hq)

typedef unsigned long long u64;
typedef unsigned int u32;

// ---------------- device scratch ----------------
__device__ float g_xg[(size_t)Bq * Tq * G4];
__device__ float g_tb[Bq * G4];
__device__ float g_hbuf[Bq * Hq];
__device__ __half g_h16hi[2 * BH];                 // f16(h)
__device__ __half g_h16lo[2 * BH];                 // f16((h - f16(h)) * 32)
__device__ __half g_w16[(size_t)G4 * Hq];          // f16(w_hh)
__device__ __nv_bfloat16 g_xeb[(size_t)Bq * Tq * Eq];
__device__ __nv_bfloat16 g_wihb[(size_t)G4 * Eq];
__device__ float g_h1[Bq * Fq];
__device__ float g_s[Fq];
__device__ float g_t[Fq];
__device__ unsigned int g_bar;

// ---------------- helpers ----------------
__device__ __forceinline__ float sigmoidf(float x) { return 1.0f / (1.0f + expf(-x)); }

__device__ __forceinline__ u32 smem_u32(const void* p) {
    u32 a; asm("{ .reg .u64 t; cvta.to.shared.u64 t, %1; cvt.u32.u64 %0, t; }" : "=r"(a) : "l"(p));
    return a;
}
__device__ __forceinline__ void ldm4(u32 &r0, u32 &r1, u32 &r2, u32 &r3, u32 addr) {
    asm volatile("ldmatrix.sync.aligned.m8n8.x4.shared.b16 {%0,%1,%2,%3}, [%4];"
        : "=r"(r0), "=r"(r1), "=r"(r2), "=r"(r3) : "r"(addr));
}
__device__ __forceinline__ void mma16816(float* d, const u32* a, u32 b0, u32 b1) {
    asm volatile("mma.sync.aligned.m16n8k16.row.col.f32.bf16.bf16.f32 "
        "{%0,%1,%2,%3}, {%4,%5,%6,%7}, {%8,%9}, {%0,%1,%2,%3};"
        : "+f"(d[0]), "+f"(d[1]), "+f"(d[2]), "+f"(d[3])
        : "r"(a[0]), "r"(a[1]), "r"(a[2]), "r"(a[3]), "r"(b0), "r"(b1));
}
__device__ __forceinline__ void mma16816h(float* d, const u32* a, u32 b0, u32 b1) {
    asm volatile("mma.sync.aligned.m16n8k16.row.col.f32.f16.f16.f32 "
        "{%0,%1,%2,%3}, {%4,%5,%6,%7}, {%8,%9}, {%0,%1,%2,%3};"
        : "+f"(d[0]), "+f"(d[1]), "+f"(d[2]), "+f"(d[3])
        : "r"(a[0]), "r"(a[1]), "r"(a[2]), "r"(a[3]), "r"(b0), "r"(b1));
}
__device__ __forceinline__ void cpa16(u32 dst, const void* src) {
    asm volatile("cp.async.cg.shared.global [%0], [%1], 16;" :: "r"(dst), "l"(src));
}
#define CP_COMMIT() asm volatile("cp.async.commit_group;" ::: "memory")
#define CP_WAIT0()  asm volatile("cp.async.wait_group 0;" ::: "memory")

// ---------------- init ----------------
__global__ void k_init() {
    int i = blockIdx.x * blockDim.x + threadIdx.x;
    if (i == 0) g_bar = 0u;
    if (i < BH) {
        g_h16hi[i] = __float2half(0.f);
        g_h16lo[i] = __float2half(0.f);
    }
}

// ---------------- w_hh prep: f16(w) ----------------
__global__ __launch_bounds__(256) void k_wprep(const float* __restrict__ w) {
    size_t i = ((size_t)blockIdx.x * 256 + threadIdx.x) * 4;
    float4 v = *(const float4*)(w + i);
    __half a[4] = {__float2half_rn(v.x), __float2half_rn(v.y),
                   __float2half_rn(v.z), __float2half_rn(v.w)};
    *(uint2*)(g_w16 + i) = *(uint2*)a;
}

// ---------------- w_ih -> bf16 ----------------
__global__ __launch_bounds__(256) void k_wihb(const float* __restrict__ w) {
    size_t i = ((size_t)blockIdx.x * 256 + threadIdx.x) * 4;
    float4 v = *(const float4*)(w + i);
    __nv_bfloat16 b[4] = {__float2bfloat16(v.x), __float2bfloat16(v.y),
                          __float2bfloat16(v.z), __float2bfloat16(v.w)};
    *(uint2*)(g_wihb + i) = *(uint2*)b;
}

// ---------------- emb gather -> bf16 ----------------
__global__ __launch_bounds__(256) void k_xeb(const int* __restrict__ x,
                                             const float* __restrict__ emb) {
    size_t idx = (size_t)blockIdx.x * 256 + threadIdx.x;
    int m = (int)(idx >> 7);
    int e4 = ((int)idx & 127) * 4;
    int row = x[m];
    float4 v = *(const float4*)(emb + (size_t)row * Eq + e4);
    __nv_bfloat16 b[4] = {__float2bfloat16(v.x), __float2bfloat16(v.y),
                          __float2bfloat16(v.z), __float2bfloat16(v.w)};
    *(uint2*)(g_xeb + (size_t)m * Eq + e4) = *(uint2*)b;
}

// ---------------- topic bias ----------------
__global__ __launch_bounds__(256) void k_topic(const float* __restrict__ x_top,
                                               const float* __restrict__ w_th,
                                               const float* __restrict__ bias) {
    __shared__ float xt[TOPq];
    int b = blockIdx.x, tid = threadIdx.x;
    if (tid < TOPq) xt[tid] = x_top[b * TOPq + tid];
    __syncthreads();
    for (int g = tid; g < G4; g += 256) {
        const float4* wr = (const float4*)(w_th + (size_t)g * TOPq);
        float s = bias[g];
        #pragma unroll
        for (int k = 0; k < TOPq / 4; k++) {
            float4 w4 = wr[k];
            s += xt[4*k]*w4.x + xt[4*k+1]*w4.y + xt[4*k+2]*w4.z + xt[4*k+3]*w4.w;
        }
        g_tb[b * G4 + g] = s;
    }
}

// ---------------- xg GEMM (bf16 tensor, cp.async; unchanged) ----------------
#define XA_STRIDE 144
#define XA_HALF   18432
#define XB_BASE   36864
#define XB_HALF   9216
#define XG_SMEM   55296

__global__ __launch_bounds__(256) void k_xg_t() {
    extern __shared__ char dsm[];
    int tid = threadIdx.x, wid = tid >> 5, lane = tid & 31;
    int n0 = blockIdx.x * 64;
    int m0 = blockIdx.y * 128;

    int arow[4], ac[4];
    #pragma unroll
    for (int i = 0; i < 4; i++) { int u = tid + i * 256; arow[i] = u >> 3; ac[i] = u & 7; }
    int brow[2], bc[2];
    #pragma unroll
    for (int i = 0; i < 2; i++) { int u = tid + i * 256; brow[i] = u >> 3; bc[i] = u & 7; }

    u32 sb = smem_u32(dsm);
    int amrow = wid * 16 + (lane & 7) + ((lane >> 3) & 1) * 8;
    u32 aAddr = sb + amrow * XA_STRIDE + (lane >> 4) * 16;
    u32 bAddr = sb + XB_BASE + lane * XA_STRIDE;

    float acc[8][4];
    #pragma unroll
    for (int i = 0; i < 8; i++) { acc[i][0]=0.f; acc[i][1]=0.f; acc[i][2]=0.f; acc[i][3]=0.f; }

    const __nv_bfloat16* Ag = g_xeb + (size_t)m0 * Eq;
    const __nv_bfloat16* Bg = g_wihb + (size_t)n0 * Eq;

    {
        u32 aS = sb, bS = sb + XB_BASE;
        #pragma unroll
        for (int i = 0; i < 4; i++)
            cpa16(aS + arow[i] * XA_STRIDE + ac[i] * 16, Ag + (size_t)arow[i] * Eq + ac[i] * 8);
        #pragma unroll
        for (int i = 0; i < 2; i++)
            cpa16(bS + brow[i] * XA_STRIDE + bc[i] * 16, Bg + (size_t)brow[i] * Eq + bc[i] * 8);
        CP_COMMIT();
    }

    for (int c = 0; c < 8; c++) {
        int buf = c & 1;
        CP_WAIT0();
        __syncthreads();
        if (c < 7) {
            int k0 = (c + 1) * 64;
            u32 aS = sb + (buf ^ 1) * XA_HALF;
            u32 bS = sb + XB_BASE + (buf ^ 1) * XB_HALF;
            #pragma unroll
            for (int i = 0; i < 4; i++)
                cpa16(aS + arow[i] * XA_STRIDE + ac[i] * 16, Ag + (size_t)arow[i] * Eq + k0 + ac[i] * 8);
            #pragma unroll
            for (int i = 0; i < 2; i++)
                cpa16(bS + brow[i] * XA_STRIDE + bc[i] * 16, Bg + (size_t)brow[i] * Eq + k0 + bc[i] * 8);
            CP_COMMIT();
        }

        u32 oA = buf * XA_HALF, oB = buf * XB_HALF;
        #pragma unroll
        for (int s = 0; s < 4; s++) {
            u32 a[4], b0[4], b1[4], b2[4], b3[4];
            ldm4(a[0], a[1], a[2], a[3], aAddr + oA + s * 32);
            ldm4(b0[0], b0[1], b0[2], b0[3], bAddr + oB + s * 32);
            ldm4(b1[0], b1[1], b1[2], b1[3], bAddr + oB + s * 32 + 16);
            ldm4(b2[0], b2[1], b2[2], b2[3], bAddr + 4608 + oB + s * 32);
            ldm4(b3[0], b3[1], b3[2], b3[3], bAddr + 4608 + oB + s * 32 + 16);
            #pragma unroll
            for (int nt = 0; nt < 4; nt++) mma16816(acc[nt], a, b0[nt], b1[nt]);
            #pragma unroll
            for (int nt = 0; nt < 4; nt++) mma16816(acc[4 + nt], a, b2[nt], b3[nt]);
        }
    }

    int g = lane >> 2, tq = lane & 3;
    int bb = m0 >> 8;
    const float* tbr = g_tb + (size_t)bb * G4 + n0;
    #pragma unroll
    for (int rr = 0; rr < 2; rr++) {
        int m = m0 + wid * 16 + g + rr * 8;
        float* orow = g_xg + (size_t)m * G4 + n0;
        #pragma unroll
        for (int nt = 0; nt < 8; nt++) {
            int nn = nt * 8 + tq * 2;
            float2 tb2 = *(const float2*)(tbr + nn);
            float2 o;
            o.x = acc[nt][rr * 2 + 0] + tb2.x;
            o.y = acc[nt][rr * 2 + 1] + tb2.y;
            *(float2*)(orow + nn) = o;
        }
    }
}

// ---------------- persistent LSTM recurrence: fp16 2-acc, 8 big chunks -----
// gate = accP + accL/32 where accP = h_hi·w16, accL = (h_lo*32)·w16.
// K=1024 in 8 chunks of 128. Single B bank shared by both passes.
// Smem: A 2 bufs x (hi 34816 + lo 34816) = 139264; B 8 x 8704 = 69632 -> 208896
#define A_STRIDE 272
#define A_HILO   34816
#define A_BUFSZ  69632
#define B_BASE   139264
#define B_CHUNK  8704
#define RNN_SMEM 208896

__global__ __launch_bounds__(256) void k_rnn() {
    extern __shared__ char dsm[];
    int tid = threadIdx.x, wid = tid >> 5, lane = tid & 31;
    int n = blockIdx.x;
    u32 sb = smem_u32(dsm);

    // A cp mapping: 128 rows x 16 quads (16B), 8 per thread per plane
    int arow[8], aq[8];
    #pragma unroll
    for (int i = 0; i < 8; i++) { int u = tid + i * 256; arow[i] = u >> 4; aq[i] = u & 15; }

    // ---- persistent B (w16 slice): 32 rows x 1024 k ----
    {
        int brow = tid >> 3, bq = tid & 7;
        size_t grow = (size_t)((brow >> 3) * Hq + n * NH + (brow & 7)) * Hq;
        u32 d = sb + B_BASE + brow * A_STRIDE;
        #pragma unroll
        for (int c = 0; c < 8; c++) {
            cpa16(d + c * B_CHUNK + bq * 16,       g_w16 + grow + c * 128 + bq * 8);
            cpa16(d + c * B_CHUNK + (bq + 8) * 16, g_w16 + grow + c * 128 + (bq + 8) * 8);
        }
        CP_COMMIT();
    }

    int amrow = wid * 16 + (lane & 7) + ((lane >> 3) & 1) * 8;
    u32 aAddr = sb + amrow * A_STRIDE + (lane >> 4) * 16;
    u32 bAddr = sb + B_BASE + lane * A_STRIDE;

    int g = lane >> 2, tq = lane & 3;
    int u0 = tq * 2;
    float creg[4] = {0.f, 0.f, 0.f, 0.f};

    CP_WAIT0();
    __syncthreads();

    for (int t = 0; t < Tq; t++) {
        int ph = t & 1;
        const __half* hh = g_h16hi + (size_t)ph * BH;
        const __half* hl = g_h16lo + (size_t)ph * BH;

        float accP[4][4], accL[4][4];
        #pragma unroll
        for (int i = 0; i < 4; i++) {
            accP[i][0]=0.f; accP[i][1]=0.f; accP[i][2]=0.f; accP[i][3]=0.f;
            accL[i][0]=0.f; accL[i][1]=0.f; accL[i][2]=0.f; accL[i][3]=0.f;
        }

        // issue chunk 0 into buf 0
        {
            u32 aH = sb, aL = sb + A_HILO;
            #pragma unroll
            for (int i = 0; i < 8; i++) {
                size_t off = (size_t)arow[i] * Hq + aq[i] * 8;
                u32 so = arow[i] * A_STRIDE + aq[i] * 16;
                cpa16(aH + so, hh + off);
                cpa16(aL + so, hl + off);
            }
            CP_COMMIT();
        }

        for (int c = 0; c < 8; c++) {
            int buf = c & 1;
            CP_WAIT0();
            __syncthreads();
            if (c < 7) {
                int k0 = (c + 1) * 128;
                u32 aH = sb + (buf ^ 1) * A_BUFSZ, aL = aH + A_HILO;
                #pragma unroll
                for (int i = 0; i < 8; i++) {
                    size_t off = (size_t)arow[i] * Hq + k0 + aq[i] * 8;
                    u32 so = arow[i] * A_STRIDE + aq[i] * 16;
                    cpa16(aH + so, hh + off);
                    cpa16(aL + so, hl + off);
                }
                CP_COMMIT();
            }

            u32 oAh = buf * A_BUFSZ;
            u32 oAl = oAh + A_HILO;
            u32 oB  = c * B_CHUNK;
            #pragma unroll
            for (int s = 0; s < 8; s++) {
                u32 ah[4], al[4], b0[4], b1[4];
                ldm4(ah[0], ah[1], ah[2], ah[3], aAddr + oAh + s * 32);
                ldm4(al[0], al[1], al[2], al[3], aAddr + oAl + s * 32);
                ldm4(b0[0], b0[1], b0[2], b0[3], bAddr + oB + s * 32);
                ldm4(b1[0], b1[1], b1[2], b1[3], bAddr + oB + s * 32 + 16);
                #pragma unroll
                for (int nt = 0; nt < 4; nt++) {
                    mma16816h(accP[nt], ah, b0[nt], b1[nt]);
                    mma16816h(accL[nt], al, b0[nt], b1[nt]);
                }
            }
        }

        // ---- epilogue (registers only; c persistent) ----
        int phn = (t + 1) & 1;
        const float LS = 1.0f / 32.0f;
        #pragma unroll
        for (int rr = 0; rr < 2; rr++) {
            int b = wid * 16 + g + rr * 8;
            const float* xr = g_xg + ((size_t)b * Tq + t) * G4 + n * NH + u0;
            float2 x0 = *(const float2*)(xr);
            float2 x1 = *(const float2*)(xr + Hq);
            float2 x2 = *(const float2*)(xr + 2 * Hq);
            float2 x3 = *(const float2*)(xr + 3 * Hq);

            float i0 = sigmoidf(accP[0][rr*2+0] + accL[0][rr*2+0] * LS + x0.x);
            float f0 = sigmoidf(accP[1][rr*2+0] + accL[1][rr*2+0] * LS + x1.x);
            float gg0 = tanhf(accP[2][rr*2+0] + accL[2][rr*2+0] * LS + x2.x);
            float o0 = sigmoidf(accP[3][rr*2+0] + accL[3][rr*2+0] * LS + x3.x);
            float i1 = sigmoidf(accP[0][rr*2+1] + accL[0][rr*2+1] * LS + x0.y);
            float f1 = sigmoidf(accP[1][rr*2+1] + accL[1][rr*2+1] * LS + x1.y);
            float gg1 = tanhf(accP[2][rr*2+1] + accL[2][rr*2+1] * LS + x2.y);
            float o1 = sigmoidf(accP[3][rr*2+1] + accL[3][rr*2+1] * LS + x3.y);

            float c0 = f0 * creg[rr*2+0] + i0 * gg0;
            float c1 = f1 * creg[rr*2+1] + i1 * gg1;
            creg[rr*2+0] = c0;
            creg[rr*2+1] = c1;
            float hx = o0 * tanhf(c0);
            float hy = o1 * tanhf(c1);

            size_t hob = (size_t)phn * BH + (size_t)b * Hq + n * NH + u0;
            __half hi0 = __float2half_rn(hx);
            __half hi1 = __float2half_rn(hy);
            __half lo0 = __float2half_rn((hx - __half2float(hi0)) * 32.0f);
            __half lo1 = __float2half_rn((hy - __half2float(hi1)) * 32.0f);
            __half2 hp = __halves2half2(hi0, hi1);
            __half2 lp = __halves2half2(lo0, lo1);
            __stcg((unsigned int*)(g_h16hi + hob), *(unsigned int*)&hp);
            __stcg((unsigned int*)(g_h16lo + hob), *(unsigned int*)&lp);

            if (t == Tq - 1) {
                float2 hv; hv.x = hx; hv.y = hy;
                *(float2*)(g_hbuf + (size_t)b * Hq + n * NH + u0) = hv;
            }
        }

        // ---- global barrier between steps ----
        if (t < Tq - 1) {
            __threadfence();
            __syncthreads();
            if (tid == 0) {
                atomicAdd(&g_bar, 1u);
                unsigned int tgt = 128u * (t + 1);
                volatile unsigned int* p = &g_bar;
                while (*p < tgt) { }
                __threadfence();
            }
            __syncthreads();
        }
    }
}

// ---------------- fc1 ----------------
__global__ __launch_bounds__(256) void k_fc1(const float* __restrict__ fc1_w,
                                             const float* __restrict__ fc1_b) {
    int b = blockIdx.y;
    int f = blockIdx.x * 8 + (threadIdx.x >> 5);
    int lane = threadIdx.x & 31;
    const float* hr = g_hbuf + (size_t)b * Hq;
    const float* wr = fc1_w + (size_t)f * Hq;
    float s = 0.f;
    for (int k = lane; k < Hq; k += 32) s += hr[k] * wr[k];
    #pragma unroll
    for (int off = 16; off; off >>= 1) s += __shfl_xor_sync(0xffffffffu, s, off);
    if (lane == 0) g_h1[b * Fq + f] = s + fc1_b[f];
}

// ---------------- BN stats ----------------
__global__ void k_bn(const float* __restrict__ gamma, const float* __restrict__ beta) {
    int f = threadIdx.x;
    float s = 0.f, ss = 0.f;
    for (int b = 0; b < Bq; b++) { float v = g_h1[b * Fq + f]; s += v; ss += v * v; }
    float mu = s * (1.f / Bq);
    float var = ss * (1.f / Bq) - mu * mu;
    float rstd = rsqrtf(var + 1e-5f);
    float sc = rstd * gamma[f];
    g_s[f] = sc;
    g_t[f] = beta[f] - mu * sc;
}

// ---------------- fc2 ----------------
__global__ __launch_bounds__(320) void k_out(const float* __restrict__ fc2_w,
                                             const float* __restrict__ fc2_b,
                                             float* __restrict__ out) {
    int b = blockIdx.x;
    int o = threadIdx.x >> 5;
    int lane = threadIdx.x & 31;
    const float* h1r = g_h1 + (size_t)b * Fq;
    const float* wr = fc2_w + (size_t)o * Fq;
    float s = 0.f;
    for (int f = lane; f < Fq; f += 32) s += (h1r[f] * g_s[f] + g_t[f]) * wr[f];
    #pragma unroll
    for (int off = 16; off; off >>= 1) s += __shfl_xor_sync(0xffffffffu, s, off);
    if (lane == 0) out[b * Oq + o] = s + fc2_b[o];
}

// ---------------- launch ----------------
extern "C" void kernel_launch(void* const* d_in, const int* in_sizes, int n_in,
                              void* d_out, int out_size) {
    const int*   x     = (const int*)  d_in[0];
    const float* x_top = (const float*)d_in[1];
    const float* emb   = (const float*)d_in[2];
    const float* w_ih  = (const float*)d_in[3];
    const float* w_hh  = (const float*)d_in[4];
    const float* w_th  = (const float*)d_in[5];
    const float* bias  = (const float*)d_in[6];
    const float* fc1_w = (const float*)d_in[7];
    const float* fc1_b = (const float*)d_in[8];
    const float* gamma = (const float*)d_in[9];
    const float* beta  = (const float*)d_in[10];
    const float* fc2_w = (const float*)d_in[11];
    const float* fc2_b = (const float*)d_in[12];
    float* out = (float*)d_out;

    cudaFuncSetAttribute(k_xg_t, cudaFuncAttributeMaxDynamicSharedMemorySize, XG_SMEM);
    cudaFuncSetAttribute(k_rnn,  cudaFuncAttributeMaxDynamicSharedMemorySize, RNN_SMEM);

    k_init<<<(BH + 255) / 256, 256>>>();
    k_wprep<<<(G4 * Hq / 4) / 256, 256>>>(w_hh);
    k_wihb<<<(G4 * Eq / 4) / 256, 256>>>(w_ih);
    k_xeb<<<(Bq * Tq * Eq / 4) / 256, 256>>>(x, emb);
    k_topic<<<Bq, 256>>>(x_top, w_th, bias);
    dim3 gxg(G4 / 64, (Bq * Tq) / 128);
    k_xg_t<<<gxg, 256, XG_SMEM>>>();
    k_rnn<<<128, 256, RNN_SMEM>>>();
    k_fc1<<<dim3(Fq / 8, Bq), 256>>>(fc1_w, fc1_b);
    k_bn<<<1, Fq>>>(gamma, beta);
    k_out<<<Bq, 320>>>(fc2_w, fc2_b, out);
}